// round 1
// baseline (speedup 1.0000x reference)
#include <cuda_runtime.h>
#include <math.h>

#define Bb 2
#define Dd 192
#define Hh 56
#define Ww 56
#define Nn 16
#define Rr 12
#define Kk 4
#define LL (Hh*Ww)      /* 3136 */
#define TP 64           /* positions per prep tile */
#define CH 44           /* R + 2N */

// ---------------- device scratch (static, no runtime alloc) ----------------
__device__ float2 g_dz[2*Bb*Kk*LL*Dd];      // (softplus(delta), delta*u) per (s,b,k,pos,d)   77MB
__device__ float2 g_B [2*Bb*Kk*LL*(Nn/2)]; // B, n-permuted pairs (n, n+8)                   3.2MB
__device__ float2 g_C [2*Bb*Kk*LL*(Nn/2)]; // C, same permutation                            3.2MB
__device__ float  g_yk[2*Bb*Kk*LL*Dd];      // per-direction scan outputs (canonical pos)    38.5MB
__device__ float  g_xT[2*Bb*LL*Dd];         // x transposed to [pos][d]                      9.6MB

// ---------------- kernel 1: projections + precompute ----------------
// grid (L/TP, B, 2 streams), 256 threads, dynamic smem
__global__ void prep_kernel(const float* __restrict__ x1, const float* __restrict__ x2,
                            const float* __restrict__ pw1, const float* __restrict__ pw2,
                            const float* __restrict__ dtw1, const float* __restrict__ dtw2,
                            const float* __restrict__ dtb1, const float* __restrict__ dtb2)
{
    extern __shared__ float sm[];
    float* xs   = sm;                    // [TP][196]  (padded rows, 16B aligned)
    float* Ws   = xs + TP*196;           // [44][192]
    float* dtws = Ws + CH*Dd;            // [192][13]  (padded)
    float* bsm  = dtws + Dd*13;          // [192]
    float* dblS = bsm + Dd;              // [44][66]

    const int t    = threadIdx.x;
    const int pos0 = blockIdx.x * TP;
    const int b    = blockIdx.y;
    const int s    = blockIdx.z;
    const float* x   = s ? x2   : x1;
    const float* pw  = s ? pw2  : pw1;
    const float* dtw = s ? dtw2 : dtw1;
    const float* dtb = s ? dtb2 : dtb1;
    const int sb = s*2 + b;

    // load x tile transposed into smem: xs[p][d]
    for (int e = t; e < Dd*TP; e += 256) {
        int d = e / TP, p = e % TP;                 // consecutive e -> consecutive p (coalesced)
        xs[p*196 + d] = x[(b*Dd + d)*LL + pos0 + p];
    }
    __syncthreads();
    // write transposed x once (used by merge kernel for the D*u term)
    if (t < Dd) {
        for (int p = 0; p < TP; p++)
            g_xT[(sb*LL + pos0 + p)*Dd + t] = xs[p*196 + t];
    }

    for (int k = 0; k < Kk; k++) {
        for (int e = t; e < CH*Dd; e += 256) Ws[e] = pw[k*CH*Dd + e];
        for (int e = t; e < Dd*Rr; e += 256) { int d = e/Rr, r = e%Rr; dtws[d*13+r] = dtw[k*Dd*Rr + e]; }
        if (t < Dd) bsm[t] = dtb[k*Dd + t];
        __syncthreads();

        // ---- dbl[c][p] = sum_d W[c][d] * x[d][p] ----
        {
            const int p  = t & 63;
            const int cb = t >> 6;                  // 0..3, c = cb + 4j, j<11 covers 44
            float acc[11];
            #pragma unroll
            for (int j = 0; j < 11; j++) acc[j] = 0.f;
            const float* xr = &xs[p*196];
            for (int d4 = 0; d4 < Dd; d4 += 4) {
                float4 xv = *(const float4*)(xr + d4);
                #pragma unroll
                for (int j = 0; j < 11; j++) {
                    float4 wv = *(const float4*)(&Ws[(cb + 4*j)*Dd + d4]);
                    acc[j] = fmaf(wv.x, xv.x, acc[j]);
                    acc[j] = fmaf(wv.y, xv.y, acc[j]);
                    acc[j] = fmaf(wv.z, xv.z, acc[j]);
                    acc[j] = fmaf(wv.w, xv.w, acc[j]);
                }
            }
            #pragma unroll
            for (int j = 0; j < 11; j++) dblS[(cb + 4*j)*66 + p] = acc[j];
        }
        __syncthreads();

        // ---- store B, C (n-permuted: pn = 2*(n%8) + n/8) ----
        {
            const int base = (sb*Kk + k)*LL + pos0;
            #pragma unroll
            for (int j = 0; j < 8; j++) {
                int e = t + 256*j;
                int which = e >> 10;                // 0: B, 1: C
                int e2 = e & 1023;
                int p = e2 >> 4, pn = e2 & 15;
                int n = (pn & 1)*8 + (pn >> 1);     // inverse permutation
                float v = dblS[(12 + (which ? 16 : 0) + n)*66 + p];
                float* dst = which ? (float*)g_C : (float*)g_B;
                dst[(base + p)*16 + pn] = v;
            }
        }

        // ---- dt = dtw @ dbl[0:12], softplus, z = dt*u ----
        if (t < Dd) {
            const int d = t;
            const int base = ((sb*Kk + k)*LL + pos0);
            for (int p = 0; p < TP; p++) {
                float a = bsm[d];
                #pragma unroll
                for (int r = 0; r < 12; r++) a = fmaf(dtws[d*13+r], dblS[r*66 + p], a);
                float sp = fmaxf(a, 0.f) + log1pf(__expf(-fabsf(a)));   // softplus, overflow-safe
                float z  = sp * xs[p*196 + d];
                g_dz[(base + p)*Dd + d] = make_float2(sp, z);
            }
        }
        __syncthreads();
    }
}

// ---------------- kernel 2: selective scan ----------------
// grid (48 d-chunks, K, S*B), 32 threads. lane = dl*8 + no; thread owns states (no, no+8) of channel d.
__global__ void scan_kernel(const float* __restrict__ A1, const float* __restrict__ A2)
{
    const int lane = threadIdx.x;
    const int dl = lane >> 3, no = lane & 7;
    const int k  = blockIdx.y;
    const int sb = blockIdx.z;
    const int s  = sb >> 1, b = sb & 1;
    const int d  = blockIdx.x*4 + dl;

    const float* Alog = s ? A2 : A1;
    const float a0 = -__expf(Alog[(k*Dd + d)*Nn + no]);
    const float a1 = -__expf(Alog[(k*Dd + d)*Nn + no + 8]);

    const int own = (sb*Kk + k)*LL;
    const int cro = (((s ^ 1)*2 + b)*Kk + k)*LL;

    float h0 = 0.f, h1 = 0.f;
    int cpos = 0, r = 0;
    const bool odd = (k & 1);
    const bool rev = (k >= 2);

    #pragma unroll 2
    for (int t = 0; t < LL; t++) {
        const int pos = rev ? (LL - 1 - cpos) : cpos;
        const float2 dzv = g_dz[(own + pos)*Dd + d];
        const float2 Bv  = g_B [(own + pos)*8 + no];
        const float2 Cv  = g_C [(cro + pos)*8 + no];
        const float e0 = __expf(dzv.x * a0);
        const float e1 = __expf(dzv.x * a1);
        h0 = fmaf(e0, h0, dzv.y * Bv.x);
        h1 = fmaf(e1, h1, dzv.y * Bv.y);
        float y = fmaf(h1, Cv.y, h0 * Cv.x);
        y += __shfl_xor_sync(0xffffffffu, y, 1);
        y += __shfl_xor_sync(0xffffffffu, y, 2);
        y += __shfl_xor_sync(0xffffffffu, y, 4);
        if (no == 0) g_yk[(own + pos)*Dd + d] = y;
        if (!odd) cpos++;
        else { r++; cpos += Ww; if (r == Hh) { r = 0; cpos -= (LL - 1); } }
    }
}

// ---------------- kernel 3: merge (sum k) + D*u + LayerNorm ----------------
// grid S*B*L rows, 192 threads (one per channel)
__global__ void merge_ln_kernel(const float* __restrict__ D1s, const float* __restrict__ D2s,
                                const float* __restrict__ lnw, const float* __restrict__ lnb,
                                float* __restrict__ out)
{
    __shared__ float red[6];
    const int rid = blockIdx.x;
    const int sb = rid / LL, pos = rid % LL;
    const int s = sb >> 1;
    const int d = threadIdx.x;
    const float* Ds = s ? D2s : D1s;

    float v = 0.f;
    #pragma unroll
    for (int k = 0; k < 4; k++) v += g_yk[((sb*Kk + k)*LL + pos)*Dd + d];
    const float Dsum = Ds[d] + Ds[Dd + d] + Ds[2*Dd + d] + Ds[3*Dd + d];
    v = fmaf(Dsum, g_xT[(sb*LL + pos)*Dd + d], v);

    // mean
    float tsum = v;
    #pragma unroll
    for (int o = 16; o; o >>= 1) tsum += __shfl_xor_sync(0xffffffffu, tsum, o);
    if ((d & 31) == 0) red[d >> 5] = tsum;
    __syncthreads();
    const float mu = (red[0]+red[1]+red[2]+red[3]+red[4]+red[5]) * (1.f/192.f);
    const float dv = v - mu;
    __syncthreads();
    // variance
    float q = dv*dv;
    #pragma unroll
    for (int o = 16; o; o >>= 1) q += __shfl_xor_sync(0xffffffffu, q, o);
    if ((d & 31) == 0) red[d >> 5] = q;
    __syncthreads();
    const float var = (red[0]+red[1]+red[2]+red[3]+red[4]+red[5]) * (1.f/192.f);

    out[rid*Dd + d] = dv * rsqrtf(var + 1e-5f) * lnw[d] + lnb[d];
}

// ---------------- launch ----------------
extern "C" void kernel_launch(void* const* d_in, const int* in_sizes, int n_in,
                              void* d_out, int out_size)
{
    const float* x1   = (const float*)d_in[0];
    const float* x2   = (const float*)d_in[1];
    const float* pw1  = (const float*)d_in[2];
    const float* pw2  = (const float*)d_in[3];
    const float* dtw1 = (const float*)d_in[4];
    const float* dtw2 = (const float*)d_in[5];
    const float* dtb1 = (const float*)d_in[6];
    const float* dtb2 = (const float*)d_in[7];
    const float* A1   = (const float*)d_in[8];
    const float* A2   = (const float*)d_in[9];
    const float* D1s  = (const float*)d_in[10];
    const float* D2s  = (const float*)d_in[11];
    const float* lnw  = (const float*)d_in[12];
    const float* lnb  = (const float*)d_in[13];
    float* out = (float*)d_out;

    const int smem = (TP*196 + CH*Dd + Dd*13 + Dd + CH*66) * (int)sizeof(float); // 106336 B
    cudaFuncSetAttribute(prep_kernel, cudaFuncAttributeMaxDynamicSharedMemorySize, smem);

    prep_kernel<<<dim3(LL/TP, Bb, 2), 256, smem>>>(x1, x2, pw1, pw2, dtw1, dtw2, dtb1, dtb2);
    scan_kernel<<<dim3(Dd/4, Kk, 2*Bb), 32>>>(A1, A2);
    merge_ln_kernel<<<2*Bb*LL, Dd>>>(D1s, D2s, lnw, lnb, out);
}

// round 2
// speedup vs baseline: 4.9046x; 4.9046x over previous
#include <cuda_runtime.h>
#include <math.h>

#define Bb 2
#define Dd 192
#define Hh 56
#define Ww 56
#define Nn 16
#define Rr 12
#define Kk 4
#define LL (Hh*Ww)      /* 3136 */
#define TP 64           /* positions per prep tile */
#define CH 44           /* R + 2N */
#define PF 16           /* scan prefetch depth; LL % PF == 0 */

// ---------------- device scratch (static, no runtime alloc) ----------------
// All per-direction arrays are stored in TRAVERSAL order (sequence index t), so the
// scan kernel is a purely affine linear loop for every direction.
__device__ float2 g_dz[2*Bb*Kk*LL*Dd + PF*Dd];   // (softplus(delta), delta*u)  ~77MB (+pad)
__device__ float2 g_BC[2*Bb*Kk*LL*16 + PF*16];   // per (row,no): {B.x,B.y},{C.x,C.y}  ~6.4MB
__device__ float  g_yk[2*Bb*Kk*LL*Dd];           // per-direction scan outputs (traversal idx)
__device__ float  g_xT[2*Bb*LL*Dd];              // x transposed to [pos][d] (canonical)

__device__ __forceinline__ float ex2(float x) {
    float r; asm("ex2.approx.ftz.f32 %0, %1;" : "=f"(r) : "f"(x)); return r;
}
__device__ __forceinline__ float lg2(float x) {
    float r; asm("lg2.approx.ftz.f32 %0, %1;" : "=f"(r) : "f"(x)); return r;
}
#define LOG2E 1.44269504088896340736f
#define LN2   0.69314718055994530942f

// traversal index of canonical pos for direction k
__device__ __forceinline__ int tau_of(int k, int pos) {
    int t1 = (pos % Ww) * Hh + pos / Ww;   // col-major index
    switch (k) {
        case 0: return pos;
        case 1: return t1;
        case 2: return LL - 1 - pos;
        default: return LL - 1 - t1;
    }
}

// ---------------- kernel 1: projections + precompute ----------------
// grid (L/TP, B, 2 streams), 256 threads, dynamic smem
__global__ void prep_kernel(const float* __restrict__ x1, const float* __restrict__ x2,
                            const float* __restrict__ pw1, const float* __restrict__ pw2,
                            const float* __restrict__ dtw1, const float* __restrict__ dtw2,
                            const float* __restrict__ dtb1, const float* __restrict__ dtb2)
{
    extern __shared__ float sm[];
    float* xs   = sm;                    // [TP][196]
    float* Ws   = xs + TP*196;           // [44][192]
    float* dtws = Ws + CH*Dd;            // [192][13]
    float* bsm  = dtws + Dd*13;          // [192]
    float* dblS = bsm + Dd;              // [44][66]

    const int t    = threadIdx.x;
    const int pos0 = blockIdx.x * TP;
    const int b    = blockIdx.y;
    const int s    = blockIdx.z;
    const float* x   = s ? x2   : x1;
    const float* pw  = s ? pw2  : pw1;
    const float* dtw = s ? dtw2 : dtw1;
    const float* dtb = s ? dtb2 : dtb1;
    const int sb  = s*2 + b;
    const int sbo = (s^1)*2 + b;     // cross-stream row base (for C)

    // load x tile transposed into smem: xs[p][d]
    for (int e = t; e < Dd*TP; e += 256) {
        int d = e / TP, p = e % TP;
        xs[p*196 + d] = x[(b*Dd + d)*LL + pos0 + p];
    }
    __syncthreads();
    // write transposed x once (canonical order; used by merge for the D*u term)
    for (int e = t; e < TP*Dd; e += 256) {
        int p = e / Dd, d = e - p*Dd;
        g_xT[(sb*LL + pos0 + p)*Dd + d] = xs[p*196 + d];
    }

    for (int k = 0; k < Kk; k++) {
        for (int e = t; e < CH*Dd; e += 256) Ws[e] = pw[k*CH*Dd + e];
        for (int e = t; e < Dd*Rr; e += 256) { int d = e/Rr, r = e%Rr; dtws[d*13+r] = dtw[k*Dd*Rr + e]; }
        if (t < Dd) bsm[t] = dtb[k*Dd + t];
        __syncthreads();

        // ---- dbl[c][p] = sum_d W[c][d] * x[d][p] ----
        {
            const int p  = t & 63;
            const int cb = t >> 6;                  // c = cb + 4j, j<11
            float acc[11];
            #pragma unroll
            for (int j = 0; j < 11; j++) acc[j] = 0.f;
            const float* xr = &xs[p*196];
            for (int d4 = 0; d4 < Dd; d4 += 4) {
                float4 xv = *(const float4*)(xr + d4);
                #pragma unroll
                for (int j = 0; j < 11; j++) {
                    float4 wv = *(const float4*)(&Ws[(cb + 4*j)*Dd + d4]);
                    acc[j] = fmaf(wv.x, xv.x, acc[j]);
                    acc[j] = fmaf(wv.y, xv.y, acc[j]);
                    acc[j] = fmaf(wv.z, xv.z, acc[j]);
                    acc[j] = fmaf(wv.w, xv.w, acc[j]);
                }
            }
            #pragma unroll
            for (int j = 0; j < 11; j++) dblS[(cb + 4*j)*66 + p] = acc[j];
        }
        __syncthreads();

        // ---- store packed B(own)/C(cross), traversal order, n-paired (no, no+8) ----
        for (int e = t; e < TP*8; e += 256) {
            int p = e >> 3, no = e & 7;
            int tauv = tau_of(k, pos0 + p);
            float2 bv = make_float2(dblS[(12+no)*66+p], dblS[(20+no)*66+p]);
            float2 cv = make_float2(dblS[(28+no)*66+p], dblS[(36+no)*66+p]);
            g_BC[((sb *Kk + k)*LL + tauv)*16 + no*2    ] = bv;   // own-stream B half
            g_BC[((sbo*Kk + k)*LL + tauv)*16 + no*2 + 1] = cv;   // cross-stream C half
        }

        // ---- dt = dtw @ dbl[0:12] + bias, softplus, z = dt*u ; traversal-order store ----
        for (int e = t; e < TP*Dd; e += 256) {
            int p = e / Dd, d = e - p*Dd;
            float a = bsm[d];
            #pragma unroll
            for (int r = 0; r < 12; r++) a = fmaf(dtws[d*13+r], dblS[r*66 + p], a);
            // softplus = max(a,0) + log(1+exp(-|a|)), fast-math version
            float em = ex2(-fabsf(a) * LOG2E);
            float sp = fmaxf(a, 0.f) + lg2(1.f + em) * LN2;
            float z  = sp * xs[p*196 + d];
            int tauv = tau_of(k, pos0 + p);
            g_dz[((sb*Kk + k)*LL + tauv)*Dd + d] = make_float2(sp, z);
        }
        __syncthreads();
    }
}

// ---------------- kernel 2: selective scan (pure linear loop, deep prefetch) ----------------
// grid (48 d-chunks, K, S*B), 32 threads.
// lane = dl*8 + no; thread owns states (no, no+8) of channel d = bx*4+dl.
__global__ void __launch_bounds__(32) scan_kernel(const float* __restrict__ A1,
                                                  const float* __restrict__ A2)
{
    const int lane = threadIdx.x;
    const int dl = lane >> 3, no = lane & 7;
    const int k  = blockIdx.y;
    const int sb = blockIdx.z;
    const int s  = sb >> 1;
    const int d  = blockIdx.x*4 + dl;

    const float* Alog = s ? A2 : A1;
    const float a0 = -__expf(Alog[(k*Dd + d)*Nn + no    ]) * LOG2E;
    const float a1 = -__expf(Alog[(k*Dd + d)*Nn + no + 8]) * LOG2E;

    const int row0 = (sb*Kk + k)*LL;
    const float2* dzp = g_dz + (size_t)row0*Dd + d;            // step: +Dd per t
    const float4* bcp = (const float4*)g_BC + (size_t)row0*8 + no;  // step: +8 per t
    float*        yp  = g_yk + (size_t)row0*Dd + d;            // step: +Dd per t

    float2 dzb[PF];
    float4 bcb[PF];
    #pragma unroll
    for (int j = 0; j < PF; j++) {
        dzb[j] = dzp[j*Dd];
        bcb[j] = bcp[j*8];
    }

    float h0 = 0.f, h1 = 0.f;
    for (int tt = 0; tt < LL; tt += PF) {
        #pragma unroll
        for (int j = 0; j < PF; j++) {
            const float2 dz = dzb[j];
            const float4 bc = bcb[j];
            const int tn = tt + PF + j;            // prefetch PF ahead (pad covers tail)
            dzb[j] = dzp[tn*Dd];
            bcb[j] = bcp[tn*8];

            const float e0 = ex2(dz.x * a0);
            const float e1 = ex2(dz.x * a1);
            h0 = fmaf(e0, h0, dz.y * bc.x);
            h1 = fmaf(e1, h1, dz.y * bc.y);
            float y = fmaf(h1, bc.w, h0 * bc.z);
            y += __shfl_xor_sync(0xffffffffu, y, 1);
            y += __shfl_xor_sync(0xffffffffu, y, 2);
            y += __shfl_xor_sync(0xffffffffu, y, 4);
            if (no == 0) yp[(tt + j)*Dd] = y;
        }
    }
}

// ---------------- kernel 3: merge (sum k) + D*u + LayerNorm ----------------
// grid S*B*L rows, 192 threads (one per channel)
__global__ void merge_ln_kernel(const float* __restrict__ D1s, const float* __restrict__ D2s,
                                const float* __restrict__ lnw, const float* __restrict__ lnb,
                                float* __restrict__ out)
{
    __shared__ float red[6];
    const int rid = blockIdx.x;
    const int sb = rid / LL, pos = rid % LL;
    const int s = sb >> 1;
    const int d = threadIdx.x;
    const float* Ds = s ? D2s : D1s;

    const int t1 = (pos % Ww) * Hh + pos / Ww;
    const int base = sb*Kk*LL;
    float v = g_yk[(size_t)(base          + pos         )*Dd + d]
            + g_yk[(size_t)(base + 1*LL   + t1          )*Dd + d]
            + g_yk[(size_t)(base + 2*LL   + (LL-1-pos)  )*Dd + d]
            + g_yk[(size_t)(base + 3*LL   + (LL-1-t1)   )*Dd + d];
    const float Dsum = Ds[d] + Ds[Dd + d] + Ds[2*Dd + d] + Ds[3*Dd + d];
    v = fmaf(Dsum, g_xT[(size_t)(sb*LL + pos)*Dd + d], v);

    float tsum = v;
    #pragma unroll
    for (int o = 16; o; o >>= 1) tsum += __shfl_xor_sync(0xffffffffu, tsum, o);
    if ((d & 31) == 0) red[d >> 5] = tsum;
    __syncthreads();
    const float mu = (red[0]+red[1]+red[2]+red[3]+red[4]+red[5]) * (1.f/192.f);
    const float dv = v - mu;
    __syncthreads();
    float q = dv*dv;
    #pragma unroll
    for (int o = 16; o; o >>= 1) q += __shfl_xor_sync(0xffffffffu, q, o);
    if ((d & 31) == 0) red[d >> 5] = q;
    __syncthreads();
    const float var = (red[0]+red[1]+red[2]+red[3]+red[4]+red[5]) * (1.f/192.f);

    out[rid*Dd + d] = dv * rsqrtf(var + 1e-5f) * lnw[d] + lnb[d];
}

// ---------------- launch ----------------
extern "C" void kernel_launch(void* const* d_in, const int* in_sizes, int n_in,
                              void* d_out, int out_size)
{
    const float* x1   = (const float*)d_in[0];
    const float* x2   = (const float*)d_in[1];
    const float* pw1  = (const float*)d_in[2];
    const float* pw2  = (const float*)d_in[3];
    const float* dtw1 = (const float*)d_in[4];
    const float* dtw2 = (const float*)d_in[5];
    const float* dtb1 = (const float*)d_in[6];
    const float* dtb2 = (const float*)d_in[7];
    const float* A1   = (const float*)d_in[8];
    const float* A2   = (const float*)d_in[9];
    const float* D1s  = (const float*)d_in[10];
    const float* D2s  = (const float*)d_in[11];
    const float* lnw  = (const float*)d_in[12];
    const float* lnb  = (const float*)d_in[13];
    float* out = (float*)d_out;

    const int smem = (TP*196 + CH*Dd + Dd*13 + Dd + CH*66) * (int)sizeof(float); // 106336 B
    cudaFuncSetAttribute(prep_kernel, cudaFuncAttributeMaxDynamicSharedMemorySize, smem);

    prep_kernel<<<dim3(LL/TP, Bb, 2), 256, smem>>>(x1, x2, pw1, pw2, dtw1, dtw2, dtb1, dtb2);
    scan_kernel<<<dim3(Dd/4, Kk, 2*Bb), 32>>>(A1, A2);
    merge_ln_kernel<<<2*Bb*LL, Dd>>>(D1s, D2s, lnw, lnb, out);
}